// round 13
// baseline (speedup 1.0000x reference)
#include <cuda_runtime.h>
#include <cuda_bf16.h>
#include <cstdint>

// Shapes fixed by the reference.
#define BATCH 4
#define SEQ   2048
#define DMODEL 1024
#define MTOT  (BATCH * SEQ)      // 8192
#define K3    (3 * DMODEL)       // 3072  (split-cat K for D=1024 GEMMs)
#define K3S   (3 * SEQ)          // 6144  (split-cat K for ctx GEMM)

// ---------------------------------------------------------------------------
// Scratch (__device__ globals — allocation-guard safe)
// ---------------------------------------------------------------------------
__device__ __nv_bfloat16 g_xs [(size_t)MTOT * K3];            // x split  (A-pattern)
__device__ __nv_bfloat16 g_Wqt[(size_t)DMODEL * K3];          // Wq^T split (B-pattern)
__device__ __nv_bfloat16 g_Wkt[(size_t)DMODEL * K3];
__device__ __nv_bfloat16 g_Wvt[(size_t)DMODEL * K3];
__device__ __nv_bfloat16 g_Wot[(size_t)DMODEL * K3];
__device__ __nv_bfloat16 g_Qs [(size_t)MTOT * K3];            // Q split (A-pattern)
__device__ __nv_bfloat16 g_Ks [(size_t)MTOT * K3];            // K split (B-pattern)
__device__ float         g_Vf [(size_t)MTOT * DMODEL];        // V fp32
__device__ __nv_bfloat16 g_Vts[(size_t)BATCH * DMODEL * K3S]; // V^T split (B-pattern)
__device__ float         g_Sc [(size_t)BATCH * SEQ * SEQ];    // scores fp32
__device__ __nv_bfloat16 g_Ps [(size_t)MTOT * K3S];           // probs split (A-pattern)
__device__ __nv_bfloat16 g_Cs [(size_t)MTOT * K3];            // ctx split (A-pattern)

// ---------------------------------------------------------------------------
// PTX helpers — ONLY baseline sm_80/sm_90 instructions (no 'a' features).
// ---------------------------------------------------------------------------
__device__ __forceinline__ uint32_t smem_to_u32(const void* p) {
    uint32_t a;
    asm("{ .reg .u64 t; cvta.to.shared.u64 t, %1; cvt.u32.u64 %0, t; }"
        : "=r"(a) : "l"(p));
    return a;
}
__device__ __forceinline__ void cp16(uint32_t dst, const void* src) {
    asm volatile("cp.async.cg.shared.global [%0], [%1], 16;"
                 :: "r"(dst), "l"(src));
}
#define CP_COMMIT() asm volatile("cp.async.commit_group;" ::: "memory")
#define CP_WAIT(n)  asm volatile("cp.async.wait_group %0;" :: "n"(n) : "memory")

__device__ __forceinline__ void ldsm4(uint32_t* r, uint32_t addr) {
    asm volatile("ldmatrix.sync.aligned.m8n8.x4.shared.b16 {%0,%1,%2,%3}, [%4];"
                 : "=r"(r[0]), "=r"(r[1]), "=r"(r[2]), "=r"(r[3]) : "r"(addr));
}
__device__ __forceinline__ void mma16816(float* c, const uint32_t* a, const uint32_t* b) {
    asm volatile(
        "mma.sync.aligned.m16n8k16.row.col.f32.bf16.bf16.f32 "
        "{%0,%1,%2,%3}, {%4,%5,%6,%7}, {%8,%9}, {%0,%1,%2,%3};"
        : "+f"(c[0]), "+f"(c[1]), "+f"(c[2]), "+f"(c[3])
        : "r"(a[0]), "r"(a[1]), "r"(a[2]), "r"(a[3]), "r"(b[0]), "r"(b[1]));
}

// SMEM tile: 128 rows x 32 bf16 (64 B/row), 4 chunks of 16B per row,
// XOR swizzle on chunk id so that cp.async stores AND ldmatrix 8-row reads
// are bank-conflict-free.
__device__ __forceinline__ uint32_t swoff(int r, int c) {
    return (uint32_t)((r << 6) + (((c ^ ((r >> 1) & 3)) & 3) << 4));
}

__device__ __forceinline__ void write_split(__nv_bfloat16* p, int KC, int patB,
                                            float v0, float v1) {
    __nv_bfloat16 h0 = __float2bfloat16(v0);
    __nv_bfloat16 h1 = __float2bfloat16(v1);
    __nv_bfloat16 l0 = __float2bfloat16(v0 - __bfloat162float(h0));
    __nv_bfloat16 l1 = __float2bfloat16(v1 - __bfloat162float(h1));
    __nv_bfloat162 hh = __halves2bfloat162(h0, h1);
    __nv_bfloat162 ll = __halves2bfloat162(l0, l1);
    *reinterpret_cast<__nv_bfloat162*>(p) = hh;
    *reinterpret_cast<__nv_bfloat162*>(p + KC)     = patB ? hh : ll;   // A:[hi|lo|hi] B:[hi|hi|lo]
    *reinterpret_cast<__nv_bfloat162*>(p + 2 * KC) = patB ? ll : hh;
}

// ---------------------------------------------------------------------------
// Warp-MMA GEMM (mma.sync bf16, fp32 accum):
//   C[m][n] = alpha * sum_k A[m][k] * B[n][k]   (A: MxKt, B: NxKt, K-major)
//   EPI==0: C fp32, row stride N, scaled by alpha
//   EPI==1: C split-cat bf16, row stride 3*KC, pattern per patB
// Block tile 128x128, BK=32, 8 warps (warp tile 64x32, 2x4 grid),
// 3-stage cp.async pipe, 48KB static SMEM, 2 CTAs/SM -> 16 warps/SM.
// ---------------------------------------------------------------------------
#define NSTAGE 3
#define STAGE_BYTES 16384            // A 8KB + B 8KB

template <int EPI>
__global__ __launch_bounds__(256, 2)
void mma_gemm(const __nv_bfloat16* __restrict__ A,
              const __nv_bfloat16* __restrict__ B,
              void* __restrict__ Cout,
              int M, int N, int Kt,
              long sA, long sB, long sC,
              float alpha, int KC, int patB)
{
    __shared__ __align__(1024) char smem[NSTAGE * STAGE_BYTES];  // 48 KB
    const uint32_t sb = smem_to_u32(smem);

    const int tid    = threadIdx.x;
    const int lane   = tid & 31;
    const int wid    = tid >> 5;
    const int warp_m = wid & 1;        // 2 x 4 warp grid, 64x32 per warp
    const int warp_n = wid >> 1;       // 0..3

    const int bz = blockIdx.z;
    const __nv_bfloat16* Ab = A + (long)bz * sA;
    const __nv_bfloat16* Bb = B + (long)bz * sB;
    const int m0 = blockIdx.y * 128;
    const int n0 = blockIdx.x * 128;

    float c[4][4][4];
#pragma unroll
    for (int mt = 0; mt < 4; mt++)
#pragma unroll
        for (int nt = 0; nt < 4; nt++)
#pragma unroll
            for (int r = 0; r < 4; r++) c[mt][nt][r] = 0.f;

    // ldmatrix per-lane address pieces
    const int a_r    = warp_m * 64 + (lane & 15);
    const int a_cbit = lane >> 4;              // 0/1 -> k-half
    const int b_r    = warp_n * 32 + ((lane >> 4) << 3) + (lane & 7);
    const int b_cbit = (lane >> 3) & 1;

    const int nit = Kt >> 5;   // BK=32

    // ---- tile loader: 128x32 bf16 each for A and B, into stage s ----
    auto load_tile = [&](int it, int s) {
        const long k0 = (long)it << 5;
        const uint32_t aB  = sb + (uint32_t)(s * STAGE_BYTES);
        const uint32_t bBs = aB + 8192u;
#pragma unroll
        for (int i = 0; i < 2; i++) {
            int t2 = tid + (i << 8);          // 0..511
            int r = t2 >> 2, cc = t2 & 3;
            cp16(aB + swoff(r, cc), Ab + (long)(m0 + r) * Kt + k0 + (cc << 3));
        }
#pragma unroll
        for (int i = 0; i < 2; i++) {
            int t2 = tid + (i << 8);
            int r = t2 >> 2, cc = t2 & 3;
            cp16(bBs + swoff(r, cc), Bb + (long)(n0 + r) * Kt + k0 + (cc << 3));
        }
        CP_COMMIT();
    };

    load_tile(0, 0);
    if (nit > 1) load_tile(1, 1);

    int s = 0;
    for (int it = 0; it < nit; ++it) {
        if (it + 2 < nit) { load_tile(it + 2, (it + 2) % NSTAGE); CP_WAIT(2); }
        else if (it + 1 < nit) { CP_WAIT(1); }
        else { CP_WAIT(0); }
        __syncthreads();

        const uint32_t aB = sb + (uint32_t)(s * STAGE_BYTES);
        const uint32_t bB = aB + 8192u;
#pragma unroll
        for (int j = 0; j < 2; j++) {          // two k16 steps
            uint32_t a[4][4], b[2][4];
#pragma unroll
            for (int mt = 0; mt < 4; mt++)
                ldsm4(a[mt], aB + swoff(a_r + mt * 16, 2 * j + a_cbit));
#pragma unroll
            for (int nq = 0; nq < 2; nq++)
                ldsm4(b[nq], bB + swoff(b_r + nq * 16, 2 * j + b_cbit));
#pragma unroll
            for (int mt = 0; mt < 4; mt++)
#pragma unroll
                for (int nt = 0; nt < 4; nt++)
                    mma16816(c[mt][nt], a[mt], &b[nt >> 1][(nt & 1) * 2]);
        }
        __syncthreads();
        s = (s + 1 == NSTAGE) ? 0 : s + 1;
    }

    // ---- epilogue ----
    const int rbase = m0 + warp_m * 64 + (lane >> 2);
    const int cbase = n0 + warp_n * 32 + ((lane & 3) << 1);

    if (EPI == 0) {
        float* C = (float*)Cout + (long)bz * sC;
#pragma unroll
        for (int mt = 0; mt < 4; mt++) {
#pragma unroll
            for (int nt = 0; nt < 4; nt++) {
                long row = rbase + mt * 16;
                long col = cbase + nt * 8;
                float2 v0, v1;
                v0.x = c[mt][nt][0] * alpha; v0.y = c[mt][nt][1] * alpha;
                v1.x = c[mt][nt][2] * alpha; v1.y = c[mt][nt][3] * alpha;
                *reinterpret_cast<float2*>(C + row * (long)N + col)       = v0;
                *reinterpret_cast<float2*>(C + (row + 8) * (long)N + col) = v1;
            }
        }
    } else {
        __nv_bfloat16* C = (__nv_bfloat16*)Cout + (long)bz * sC;
        const long rs = 3L * KC;
#pragma unroll
        for (int mt = 0; mt < 4; mt++) {
#pragma unroll
            for (int nt = 0; nt < 4; nt++) {
                long row = rbase + mt * 16;
                long col = cbase + nt * 8;
                write_split(C + row * rs + col,       KC, patB, c[mt][nt][0], c[mt][nt][1]);
                write_split(C + (row + 8) * rs + col, KC, patB, c[mt][nt][2], c[mt][nt][3]);
            }
        }
    }
}

// ---------------------------------------------------------------------------
// Prep: x fp32 [R][1024] -> split-cat bf16 [R][3072], A-pattern [hi|lo|hi]
// ---------------------------------------------------------------------------
__global__ __launch_bounds__(256)
void split_x_kernel(const float* __restrict__ in, __nv_bfloat16* __restrict__ out)
{
    long i4 = (long)blockIdx.x * blockDim.x + threadIdx.x;
    long base = i4 * 4;
    long r = base >> 10;
    int  k = (int)(base & 1023);
    float4 v = *reinterpret_cast<const float4*>(in + base);
    __nv_bfloat16 h0 = __float2bfloat16(v.x), h1 = __float2bfloat16(v.y);
    __nv_bfloat16 h2 = __float2bfloat16(v.z), h3 = __float2bfloat16(v.w);
    __nv_bfloat16 l0 = __float2bfloat16(v.x - __bfloat162float(h0));
    __nv_bfloat16 l1 = __float2bfloat16(v.y - __bfloat162float(h1));
    __nv_bfloat16 l2 = __float2bfloat16(v.z - __bfloat162float(h2));
    __nv_bfloat16 l3 = __float2bfloat16(v.w - __bfloat162float(h3));
    __nv_bfloat16* row = out + r * (long)K3;
    *reinterpret_cast<__nv_bfloat162*>(row + k)              = __halves2bfloat162(h0, h1);
    *reinterpret_cast<__nv_bfloat162*>(row + k + 2)          = __halves2bfloat162(h2, h3);
    *reinterpret_cast<__nv_bfloat162*>(row + DMODEL + k)     = __halves2bfloat162(l0, l1);
    *reinterpret_cast<__nv_bfloat162*>(row + DMODEL + k + 2) = __halves2bfloat162(l2, l3);
    *reinterpret_cast<__nv_bfloat162*>(row + 2*DMODEL + k)     = __halves2bfloat162(h0, h1);
    *reinterpret_cast<__nv_bfloat162*>(row + 2*DMODEL + k + 2) = __halves2bfloat162(h2, h3);
}

// ---------------------------------------------------------------------------
// Prep: fused 4-weight transpose + split, B-pattern [hi|hi|lo].
// ---------------------------------------------------------------------------
struct WPtrs {
    const float* in[4];
    __nv_bfloat16* out[4];
};

__global__ __launch_bounds__(256)
void transpose_split4_kernel(WPtrs p)
{
    __shared__ float t[32][33];
    const float* in        = p.in[blockIdx.z];
    __nv_bfloat16* out     = p.out[blockIdx.z];
    const int r0 = blockIdx.y * 32, c0 = blockIdx.x * 32;
    const int tx = threadIdx.x, ty = threadIdx.y;   // (32, 8)
#pragma unroll
    for (int i = 0; i < 4; i++)
        t[ty + i * 8][tx] = in[(long)(r0 + ty + i * 8) * DMODEL + c0 + tx];
    __syncthreads();
#pragma unroll
    for (int i = 0; i < 4; i++) {
        const int n = c0 + ty + i * 8;
        const int r = r0 + tx;
        float v = t[tx][ty + i * 8];
        __nv_bfloat16 h = __float2bfloat16(v);
        __nv_bfloat16 l = __float2bfloat16(v - __bfloat162float(h));
        __nv_bfloat16* row = out + (long)n * K3;
        row[r]              = h;
        row[DMODEL + r]     = h;
        row[2 * DMODEL + r] = l;
    }
}

// ---------------------------------------------------------------------------
// Prep: transpose + split, B-pattern [hi|hi|lo] (for V^T, per batch).
// ---------------------------------------------------------------------------
__global__ __launch_bounds__(256)
void transpose_split_kernel(const float* __restrict__ in, __nv_bfloat16* __restrict__ out,
                            int R, int C, long sIn, long sOut)
{
    __shared__ float t[32][33];
    in  += (long)blockIdx.z * sIn;
    out += (long)blockIdx.z * sOut;
    const int r0 = blockIdx.y * 32, c0 = blockIdx.x * 32;
    const int tx = threadIdx.x, ty = threadIdx.y;   // (32, 8)
#pragma unroll
    for (int i = 0; i < 4; i++)
        t[ty + i * 8][tx] = in[(long)(r0 + ty + i * 8) * C + c0 + tx];
    __syncthreads();
#pragma unroll
    for (int i = 0; i < 4; i++) {
        const int n = c0 + ty + i * 8;
        const int r = r0 + tx;
        float v = t[tx][ty + i * 8];
        __nv_bfloat16 h = __float2bfloat16(v);
        __nv_bfloat16 l = __float2bfloat16(v - __bfloat162float(h));
        __nv_bfloat16* row = out + (long)n * (3L * R);
        row[r]          = h;
        row[R + r]      = h;
        row[2L * R + r] = l;
    }
}

// ---------------------------------------------------------------------------
// Softmax over rows of 2048, writes split-cat bf16 probs (A-pattern).
// ---------------------------------------------------------------------------
__global__ __launch_bounds__(256)
void softmax_split_kernel(const float* __restrict__ S, __nv_bfloat16* __restrict__ P)
{
    const float* row = S + (long)blockIdx.x * SEQ;
    __nv_bfloat16* prow = P + (long)blockIdx.x * K3S;
    const int t = threadIdx.x;
    __shared__ float red[8];

    float v[8];
    float mx = -1e30f;
#pragma unroll
    for (int i = 0; i < 8; i++) { v[i] = row[t + i * 256]; mx = fmaxf(mx, v[i]); }
#pragma unroll
    for (int o = 16; o > 0; o >>= 1) mx = fmaxf(mx, __shfl_xor_sync(0xffffffffu, mx, o));
    if ((t & 31) == 0) red[t >> 5] = mx;
    __syncthreads();
    mx = red[0];
#pragma unroll
    for (int i = 1; i < 8; i++) mx = fmaxf(mx, red[i]);
    __syncthreads();

    float sum = 0.f;
#pragma unroll
    for (int i = 0; i < 8; i++) { v[i] = __expf(v[i] - mx); sum += v[i]; }
#pragma unroll
    for (int o = 16; o > 0; o >>= 1) sum += __shfl_xor_sync(0xffffffffu, sum, o);
    if ((t & 31) == 0) red[t >> 5] = sum;
    __syncthreads();
    float tot = 0.f;
#pragma unroll
    for (int i = 0; i < 8; i++) tot += red[i];
    const float inv = 1.f / tot;

#pragma unroll
    for (int i = 0; i < 8; i++) {
        int j = t + i * 256;
        float p = v[i] * inv;
        __nv_bfloat16 h = __float2bfloat16(p);
        __nv_bfloat16 l = __float2bfloat16(p - __bfloat162float(h));
        prow[j]            = h;   // [hi|lo|hi]
        prow[SEQ + j]      = l;
        prow[2 * SEQ + j]  = h;
    }
}

// ---------------------------------------------------------------------------
// LayerNorm over DMODEL=1024, in place.
// ---------------------------------------------------------------------------
__global__ __launch_bounds__(256)
void ln_kernel(float* __restrict__ H, const float* __restrict__ gamma,
               const float* __restrict__ beta)
{
    float* row = H + (long)blockIdx.x * DMODEL;
    const int t = threadIdx.x;
    __shared__ float redS[8];
    __shared__ float redQ[8];

    float4 v = reinterpret_cast<const float4*>(row)[t];
    float s  = v.x + v.y + v.z + v.w;
    float sq = v.x * v.x + v.y * v.y + v.z * v.z + v.w * v.w;
#pragma unroll
    for (int o = 16; o > 0; o >>= 1) {
        s  += __shfl_xor_sync(0xffffffffu, s, o);
        sq += __shfl_xor_sync(0xffffffffu, sq, o);
    }
    if ((t & 31) == 0) { redS[t >> 5] = s; redQ[t >> 5] = sq; }
    __syncthreads();
    float stot = 0.f, qtot = 0.f;
#pragma unroll
    for (int i = 0; i < 8; i++) { stot += redS[i]; qtot += redQ[i]; }

    const float mu  = stot * (1.0f / DMODEL);
    const float var = qtot * (1.0f / DMODEL) - mu * mu;
    const float inv = rsqrtf(var + 1e-5f);

    float4 gv = reinterpret_cast<const float4*>(gamma)[t];
    float4 bv = reinterpret_cast<const float4*>(beta)[t];
    float4 o;
    o.x = (v.x - mu) * inv * gv.x + bv.x;
    o.y = (v.y - mu) * inv * gv.y + bv.y;
    o.z = (v.z - mu) * inv * gv.z + bv.z;
    o.w = (v.w - mu) * inv * gv.w + bv.w;
    reinterpret_cast<float4*>(row)[t] = o;
}

// ---------------------------------------------------------------------------
// Launch
// ---------------------------------------------------------------------------
extern "C" void kernel_launch(void* const* d_in, const int* in_sizes, int n_in,
                              void* d_out, int out_size)
{
    const float* x     = (const float*)d_in[0];
    const float* Wq    = (const float*)d_in[1];
    const float* Wk    = (const float*)d_in[2];
    const float* Wv    = (const float*)d_in[3];
    const float* Wo    = (const float*)d_in[4];
    const float* gamma = (const float*)d_in[5];
    const float* beta  = (const float*)d_in[6];
    float* out = (float*)d_out;

    __nv_bfloat16 *pxs, *pWqt, *pWkt, *pWvt, *pWot, *pQs, *pKs, *pVts, *pPs, *pCs;
    float *pVf, *pSc;
    cudaGetSymbolAddress((void**)&pxs,  g_xs);
    cudaGetSymbolAddress((void**)&pWqt, g_Wqt);
    cudaGetSymbolAddress((void**)&pWkt, g_Wkt);
    cudaGetSymbolAddress((void**)&pWvt, g_Wvt);
    cudaGetSymbolAddress((void**)&pWot, g_Wot);
    cudaGetSymbolAddress((void**)&pQs,  g_Qs);
    cudaGetSymbolAddress((void**)&pKs,  g_Ks);
    cudaGetSymbolAddress((void**)&pVf,  g_Vf);
    cudaGetSymbolAddress((void**)&pVts, g_Vts);
    cudaGetSymbolAddress((void**)&pSc,  g_Sc);
    cudaGetSymbolAddress((void**)&pPs,  g_Ps);
    cudaGetSymbolAddress((void**)&pCs,  g_Cs);

    // --- prep operands (2 launches) ---
    split_x_kernel<<<(MTOT * DMODEL / 4) / 256, 256>>>(x, pxs);
    WPtrs wp;
    wp.in[0] = Wq;  wp.out[0] = pWqt;
    wp.in[1] = Wk;  wp.out[1] = pWkt;
    wp.in[2] = Wv;  wp.out[2] = pWvt;
    wp.in[3] = Wo;  wp.out[3] = pWot;
    dim3 tb(32, 8);
    transpose_split4_kernel<<<dim3(32, 32, 4), tb>>>(wp);

    // --- QKV projections (K'=3072) ---
    dim3 g1(DMODEL / 128, MTOT / 128, 1);     // (8, 64, 1)
    mma_gemm<1><<<g1, 256>>>(pxs, pWqt, pQs, MTOT, DMODEL, K3,
                             0, 0, 0, 1.f, DMODEL, /*patB=*/0);
    mma_gemm<1><<<g1, 256>>>(pxs, pWkt, pKs, MTOT, DMODEL, K3,
                             0, 0, 0, 1.f, DMODEL, /*patB=*/1);
    mma_gemm<0><<<g1, 256>>>(pxs, pWvt, pVf, MTOT, DMODEL, K3,
                             0, 0, 0, 1.f, 0, 0);

    // V^T split per batch
    transpose_split_kernel<<<dim3(DMODEL / 32, SEQ / 32, BATCH), tb>>>(
        pVf, pVts, SEQ, DMODEL, (long)SEQ * DMODEL, (long)DMODEL * K3S);

    // --- scores = (Q K^T)/sqrt(dk), per batch ---
    dim3 g2(SEQ / 128, SEQ / 128, BATCH);     // (16, 16, 4)
    mma_gemm<0><<<g2, 256>>>(pQs, pKs, pSc, SEQ, SEQ, K3,
                             (long)SEQ * K3, (long)SEQ * K3,
                             (long)SEQ * SEQ, 0.03125f, 0, 0);

    // --- softmax -> split probs ---
    softmax_split_kernel<<<MTOT, 256>>>(pSc, pPs);

    // --- ctx = P V, per batch (K'=6144) ---
    dim3 g3(DMODEL / 128, SEQ / 128, BATCH);  // (8, 16, 4)
    mma_gemm<1><<<g3, 256>>>(pPs, pVts, pCs, SEQ, DMODEL, K3S,
                             (long)SEQ * K3S, (long)DMODEL * K3S,
                             (long)SEQ * K3, 1.f, DMODEL, /*patB=*/0);

    // --- out proj -> d_out, then LN ---
    mma_gemm<0><<<g1, 256>>>(pCs, pWot, out, MTOT, DMODEL, K3,
                             0, 0, 0, 1.f, 0, 0);
    ln_kernel<<<MTOT, 256>>>(out, gamma, beta);
}

// round 15
// speedup vs baseline: 1.2164x; 1.2164x over previous
#include <cuda_runtime.h>
#include <cuda_bf16.h>
#include <cstdint>

// Shapes fixed by the reference.
#define BATCH 4
#define SEQ   2048
#define DMODEL 1024
#define MTOT  (BATCH * SEQ)      // 8192
#define K3    (3 * DMODEL)       // 3072  (split-cat K for D=1024 GEMMs)
#define K3S   (3 * SEQ)          // 6144  (split-cat K for ctx GEMM)

// ---------------------------------------------------------------------------
// Scratch (__device__ globals — allocation-guard safe)
// ---------------------------------------------------------------------------
__device__ __nv_bfloat16 g_xs   [(size_t)MTOT * K3];            // x split (A-pattern)
__device__ __nv_bfloat16 g_Wqkvt[(size_t)(3 * DMODEL) * K3];    // [Wq^T;Wk^T;Wv^T] split (B-pattern)
__device__ __nv_bfloat16 g_Wot  [(size_t)DMODEL * K3];
__device__ __nv_bfloat16 g_Qs   [(size_t)MTOT * K3];            // Q split (A-pattern)
__device__ __nv_bfloat16 g_Ks   [(size_t)MTOT * K3];            // K split (B-pattern)
__device__ float         g_Vf   [(size_t)MTOT * DMODEL];        // V fp32
__device__ __nv_bfloat16 g_Vts  [(size_t)BATCH * DMODEL * K3S]; // V^T split (B-pattern)
__device__ float         g_Sc   [(size_t)BATCH * SEQ * SEQ];    // scores fp32
__device__ __nv_bfloat16 g_Ps   [(size_t)MTOT * K3S];           // probs split (A-pattern)
__device__ __nv_bfloat16 g_Cs   [(size_t)MTOT * K3];            // ctx split (A-pattern)

// ---------------------------------------------------------------------------
// PTX helpers — ONLY baseline sm_80/sm_90 instructions (no 'a' features).
// ---------------------------------------------------------------------------
__device__ __forceinline__ uint32_t smem_to_u32(const void* p) {
    uint32_t a;
    asm("{ .reg .u64 t; cvta.to.shared.u64 t, %1; cvt.u32.u64 %0, t; }"
        : "=r"(a) : "l"(p));
    return a;
}
__device__ __forceinline__ void cp16(uint32_t dst, const void* src) {
    asm volatile("cp.async.cg.shared.global [%0], [%1], 16;"
                 :: "r"(dst), "l"(src));
}
#define CP_COMMIT() asm volatile("cp.async.commit_group;" ::: "memory")
#define CP_WAIT(n)  asm volatile("cp.async.wait_group %0;" :: "n"(n) : "memory")

__device__ __forceinline__ void ldsm4(uint32_t* r, uint32_t addr) {
    asm volatile("ldmatrix.sync.aligned.m8n8.x4.shared.b16 {%0,%1,%2,%3}, [%4];"
                 : "=r"(r[0]), "=r"(r[1]), "=r"(r[2]), "=r"(r[3]) : "r"(addr));
}
__device__ __forceinline__ void mma16816(float* c, const uint32_t* a, const uint32_t* b) {
    asm volatile(
        "mma.sync.aligned.m16n8k16.row.col.f32.bf16.bf16.f32 "
        "{%0,%1,%2,%3}, {%4,%5,%6,%7}, {%8,%9}, {%0,%1,%2,%3};"
        : "+f"(c[0]), "+f"(c[1]), "+f"(c[2]), "+f"(c[3])
        : "r"(a[0]), "r"(a[1]), "r"(a[2]), "r"(a[3]), "r"(b[0]), "r"(b[1]));
}

// SMEM tile: 128 rows x 32 bf16 (64 B/row), 4 chunks of 16B per row,
// XOR swizzle on chunk id so that cp.async stores AND ldmatrix 8-row reads
// are bank-conflict-free.
__device__ __forceinline__ uint32_t swoff(int r, int c) {
    return (uint32_t)((r << 6) + (((c ^ ((r >> 1) & 3)) & 3) << 4));
}

__device__ __forceinline__ void write_split(__nv_bfloat16* p, int KC, int patB,
                                            float v0, float v1) {
    __nv_bfloat16 h0 = __float2bfloat16(v0);
    __nv_bfloat16 h1 = __float2bfloat16(v1);
    __nv_bfloat16 l0 = __float2bfloat16(v0 - __bfloat162float(h0));
    __nv_bfloat16 l1 = __float2bfloat16(v1 - __bfloat162float(h1));
    __nv_bfloat162 hh = __halves2bfloat162(h0, h1);
    __nv_bfloat162 ll = __halves2bfloat162(l0, l1);
    *reinterpret_cast<__nv_bfloat162*>(p) = hh;
    *reinterpret_cast<__nv_bfloat162*>(p + KC)     = patB ? hh : ll;   // A:[hi|lo|hi] B:[hi|hi|lo]
    *reinterpret_cast<__nv_bfloat162*>(p + 2 * KC) = patB ? ll : hh;
}

// ---------------------------------------------------------------------------
// Warp-MMA GEMM (mma.sync bf16, fp32 accum) — round-9 engine (measured best):
//   C[m][n] = alpha * sum_k A[m][k] * B[n][k]   (A: MxKt, B: NxKt, K-major)
//   EPI==0: C fp32, row stride N, scaled by alpha
//   EPI==1: C split-cat bf16, row stride 3*KC, pattern per patB
//   EPI==2: fused-QKV epilogue: n-section 0 -> g_Qs (A-pat), 1 -> g_Ks (B-pat),
//           2 -> g_Vf (fp32). BN=128 tiles never straddle 1024-aligned sections.
// Block tile 128x128, BK=32, 4 warps (warp tile 64x64), 3-stage cp.async pipe.
// ---------------------------------------------------------------------------
#define NSTAGE 3
#define STAGE_BYTES 16384            // A 8KB + B 8KB

template <int EPI>
__global__ __launch_bounds__(128, 2)
void mma_gemm(const __nv_bfloat16* __restrict__ A,
              const __nv_bfloat16* __restrict__ B,
              void* __restrict__ Cout,
              int M, int N, int Kt,
              long sA, long sB, long sC,
              float alpha, int KC, int patB)
{
    __shared__ __align__(1024) char smem[NSTAGE * STAGE_BYTES];  // 48 KB
    const uint32_t sb = smem_to_u32(smem);

    const int tid    = threadIdx.x;
    const int lane   = tid & 31;
    const int wid    = tid >> 5;
    const int warp_m = wid & 1;        // 2 x 2 warp grid, 64x64 per warp
    const int warp_n = wid >> 1;

    const int bz = blockIdx.z;
    const __nv_bfloat16* Ab = A + (long)bz * sA;
    const __nv_bfloat16* Bb = B + (long)bz * sB;
    const int m0 = blockIdx.y * 128;
    const int n0 = blockIdx.x * 128;

    float c[4][8][4];
#pragma unroll
    for (int mt = 0; mt < 4; mt++)
#pragma unroll
        for (int nt = 0; nt < 8; nt++)
#pragma unroll
            for (int r = 0; r < 4; r++) c[mt][nt][r] = 0.f;

    // ldmatrix per-lane address pieces
    const int a_r    = warp_m * 64 + (lane & 15);
    const int a_cbit = lane >> 4;              // 0/1 -> k-half
    const int b_r    = warp_n * 64 + ((lane >> 4) << 3) + (lane & 7);
    const int b_cbit = (lane >> 3) & 1;

    const int nit = Kt >> 5;   // BK=32

    // ---- tile loader: 128x32 bf16 each for A and B, into stage s ----
    auto load_tile = [&](int it, int s) {
        const long k0 = (long)it << 5;
        const uint32_t aB  = sb + (uint32_t)(s * STAGE_BYTES);
        const uint32_t bBs = aB + 8192u;
#pragma unroll
        for (int i = 0; i < 4; i++) {
            int t2 = tid + (i << 7);
            int r = t2 >> 2, cc = t2 & 3;
            cp16(aB + swoff(r, cc), Ab + (long)(m0 + r) * Kt + k0 + (cc << 3));
        }
#pragma unroll
        for (int i = 0; i < 4; i++) {
            int t2 = tid + (i << 7);
            int r = t2 >> 2, cc = t2 & 3;
            cp16(bBs + swoff(r, cc), Bb + (long)(n0 + r) * Kt + k0 + (cc << 3));
        }
        CP_COMMIT();
    };

    load_tile(0, 0);
    if (nit > 1) load_tile(1, 1);

    int s = 0;
    for (int it = 0; it < nit; ++it) {
        if (it + 2 < nit) { load_tile(it + 2, (it + 2) % NSTAGE); CP_WAIT(2); }
        else if (it + 1 < nit) { CP_WAIT(1); }
        else { CP_WAIT(0); }
        __syncthreads();

        const uint32_t aB = sb + (uint32_t)(s * STAGE_BYTES);
        const uint32_t bB = aB + 8192u;
#pragma unroll
        for (int j = 0; j < 2; j++) {          // two k16 steps
            uint32_t a[4][4], b[4][4];
#pragma unroll
            for (int mt = 0; mt < 4; mt++)
                ldsm4(a[mt], aB + swoff(a_r + mt * 16, 2 * j + a_cbit));
#pragma unroll
            for (int nq = 0; nq < 4; nq++)
                ldsm4(b[nq], bB + swoff(b_r + nq * 16, 2 * j + b_cbit));
#pragma unroll
            for (int mt = 0; mt < 4; mt++)
#pragma unroll
                for (int nt = 0; nt < 8; nt++)
                    mma16816(c[mt][nt], a[mt], &b[nt >> 1][(nt & 1) * 2]);
        }
        __syncthreads();
        s = (s + 1 == NSTAGE) ? 0 : s + 1;
    }

    // ---- epilogue ----
    const int rbase = m0 + warp_m * 64 + (lane >> 2);
    const int cbase = n0 + warp_n * 64 + ((lane & 3) << 1);

    if (EPI == 0) {
        float* C = (float*)Cout + (long)bz * sC;
#pragma unroll
        for (int mt = 0; mt < 4; mt++) {
#pragma unroll
            for (int nt = 0; nt < 8; nt++) {
                long row = rbase + mt * 16;
                long col = cbase + nt * 8;
                float2 v0, v1;
                v0.x = c[mt][nt][0] * alpha; v0.y = c[mt][nt][1] * alpha;
                v1.x = c[mt][nt][2] * alpha; v1.y = c[mt][nt][3] * alpha;
                *reinterpret_cast<float2*>(C + row * (long)N + col)       = v0;
                *reinterpret_cast<float2*>(C + (row + 8) * (long)N + col) = v1;
            }
        }
    } else if (EPI == 1) {
        __nv_bfloat16* C = (__nv_bfloat16*)Cout + (long)bz * sC;
        const long rs = 3L * KC;
#pragma unroll
        for (int mt = 0; mt < 4; mt++) {
#pragma unroll
            for (int nt = 0; nt < 8; nt++) {
                long row = rbase + mt * 16;
                long col = cbase + nt * 8;
                write_split(C + row * rs + col,       KC, patB, c[mt][nt][0], c[mt][nt][1]);
                write_split(C + (row + 8) * rs + col, KC, patB, c[mt][nt][2], c[mt][nt][3]);
            }
        }
    } else {
        // EPI == 2: fused QKV. sec: 0=Q (A-pat split), 1=K (B-pat split), 2=V (fp32)
        const int sec  = n0 >> 10;
        const int lcb  = (n0 & 1023) + warp_n * 64 + ((lane & 3) << 1);
        if (sec == 2) {
#pragma unroll
            for (int mt = 0; mt < 4; mt++) {
#pragma unroll
                for (int nt = 0; nt < 8; nt++) {
                    long row = rbase + mt * 16;
                    long col = lcb + nt * 8;
                    float2 v0, v1;
                    v0.x = c[mt][nt][0]; v0.y = c[mt][nt][1];
                    v1.x = c[mt][nt][2]; v1.y = c[mt][nt][3];
                    *reinterpret_cast<float2*>(g_Vf + row * DMODEL + col)       = v0;
                    *reinterpret_cast<float2*>(g_Vf + (row + 8) * DMODEL + col) = v1;
                }
            }
        } else {
            __nv_bfloat16* C = (sec == 0) ? g_Qs : g_Ks;
            const int pb = sec;          // Q: patB=0 (A-pattern), K: patB=1 (B-pattern)
#pragma unroll
            for (int mt = 0; mt < 4; mt++) {
#pragma unroll
                for (int nt = 0; nt < 8; nt++) {
                    long row = rbase + mt * 16;
                    long col = lcb + nt * 8;
                    write_split(C + row * (long)K3 + col,       DMODEL, pb, c[mt][nt][0], c[mt][nt][1]);
                    write_split(C + (row + 8) * (long)K3 + col, DMODEL, pb, c[mt][nt][2], c[mt][nt][3]);
                }
            }
        }
    }
}

// ---------------------------------------------------------------------------
// Prep: x fp32 [R][1024] -> split-cat bf16 [R][3072], A-pattern [hi|lo|hi]
// ---------------------------------------------------------------------------
__global__ __launch_bounds__(256)
void split_x_kernel(const float* __restrict__ in, __nv_bfloat16* __restrict__ out)
{
    long i4 = (long)blockIdx.x * blockDim.x + threadIdx.x;
    long base = i4 * 4;
    long r = base >> 10;
    int  k = (int)(base & 1023);
    float4 v = *reinterpret_cast<const float4*>(in + base);
    __nv_bfloat16 h0 = __float2bfloat16(v.x), h1 = __float2bfloat16(v.y);
    __nv_bfloat16 h2 = __float2bfloat16(v.z), h3 = __float2bfloat16(v.w);
    __nv_bfloat16 l0 = __float2bfloat16(v.x - __bfloat162float(h0));
    __nv_bfloat16 l1 = __float2bfloat16(v.y - __bfloat162float(h1));
    __nv_bfloat16 l2 = __float2bfloat16(v.z - __bfloat162float(h2));
    __nv_bfloat16 l3 = __float2bfloat16(v.w - __bfloat162float(h3));
    __nv_bfloat16* row = out + r * (long)K3;
    *reinterpret_cast<__nv_bfloat162*>(row + k)              = __halves2bfloat162(h0, h1);
    *reinterpret_cast<__nv_bfloat162*>(row + k + 2)          = __halves2bfloat162(h2, h3);
    *reinterpret_cast<__nv_bfloat162*>(row + DMODEL + k)     = __halves2bfloat162(l0, l1);
    *reinterpret_cast<__nv_bfloat162*>(row + DMODEL + k + 2) = __halves2bfloat162(l2, l3);
    *reinterpret_cast<__nv_bfloat162*>(row + 2*DMODEL + k)     = __halves2bfloat162(h0, h1);
    *reinterpret_cast<__nv_bfloat162*>(row + 2*DMODEL + k + 2) = __halves2bfloat162(h2, h3);
}

// ---------------------------------------------------------------------------
// Prep: fused 4-weight transpose + split, B-pattern [hi|hi|lo].
//   z=0..2 -> sections of g_Wqkvt, z=3 -> g_Wot.
// ---------------------------------------------------------------------------
struct WPtrs {
    const float* in[4];
    __nv_bfloat16* out[4];
};

__global__ __launch_bounds__(256)
void transpose_split4_kernel(WPtrs p)
{
    __shared__ float t[32][33];
    const float* in        = p.in[blockIdx.z];
    __nv_bfloat16* out     = p.out[blockIdx.z];
    const int r0 = blockIdx.y * 32, c0 = blockIdx.x * 32;
    const int tx = threadIdx.x, ty = threadIdx.y;   // (32, 8)
#pragma unroll
    for (int i = 0; i < 4; i++)
        t[ty + i * 8][tx] = in[(long)(r0 + ty + i * 8) * DMODEL + c0 + tx];
    __syncthreads();
#pragma unroll
    for (int i = 0; i < 4; i++) {
        const int n = c0 + ty + i * 8;
        const int r = r0 + tx;
        float v = t[tx][ty + i * 8];
        __nv_bfloat16 h = __float2bfloat16(v);
        __nv_bfloat16 l = __float2bfloat16(v - __bfloat162float(h));
        __nv_bfloat16* row = out + (long)n * K3;
        row[r]              = h;
        row[DMODEL + r]     = h;
        row[2 * DMODEL + r] = l;
    }
}

// ---------------------------------------------------------------------------
// Prep: transpose + split, B-pattern [hi|hi|lo] (for V^T, per batch).
// ---------------------------------------------------------------------------
__global__ __launch_bounds__(256)
void transpose_split_kernel(const float* __restrict__ in, __nv_bfloat16* __restrict__ out,
                            int R, int C, long sIn, long sOut)
{
    __shared__ float t[32][33];
    in  += (long)blockIdx.z * sIn;
    out += (long)blockIdx.z * sOut;
    const int r0 = blockIdx.y * 32, c0 = blockIdx.x * 32;
    const int tx = threadIdx.x, ty = threadIdx.y;   // (32, 8)
#pragma unroll
    for (int i = 0; i < 4; i++)
        t[ty + i * 8][tx] = in[(long)(r0 + ty + i * 8) * C + c0 + tx];
    __syncthreads();
#pragma unroll
    for (int i = 0; i < 4; i++) {
        const int n = c0 + ty + i * 8;
        const int r = r0 + tx;
        float v = t[tx][ty + i * 8];
        __nv_bfloat16 h = __float2bfloat16(v);
        __nv_bfloat16 l = __float2bfloat16(v - __bfloat162float(h));
        __nv_bfloat16* row = out + (long)n * (3L * R);
        row[r]          = h;
        row[R + r]      = h;
        row[2L * R + r] = l;
    }
}

// ---------------------------------------------------------------------------
// Softmax over rows of 2048, writes split-cat bf16 probs (A-pattern).
// ---------------------------------------------------------------------------
__global__ __launch_bounds__(256)
void softmax_split_kernel(const float* __restrict__ S, __nv_bfloat16* __restrict__ P)
{
    const float* row = S + (long)blockIdx.x * SEQ;
    __nv_bfloat16* prow = P + (long)blockIdx.x * K3S;
    const int t = threadIdx.x;
    __shared__ float red[8];

    float v[8];
    float mx = -1e30f;
#pragma unroll
    for (int i = 0; i < 8; i++) { v[i] = row[t + i * 256]; mx = fmaxf(mx, v[i]); }
#pragma unroll
    for (int o = 16; o > 0; o >>= 1) mx = fmaxf(mx, __shfl_xor_sync(0xffffffffu, mx, o));
    if ((t & 31) == 0) red[t >> 5] = mx;
    __syncthreads();
    mx = red[0];
#pragma unroll
    for (int i = 1; i < 8; i++) mx = fmaxf(mx, red[i]);
    __syncthreads();

    float sum = 0.f;
#pragma unroll
    for (int i = 0; i < 8; i++) { v[i] = __expf(v[i] - mx); sum += v[i]; }
#pragma unroll
    for (int o = 16; o > 0; o >>= 1) sum += __shfl_xor_sync(0xffffffffu, sum, o);
    if ((t & 31) == 0) red[t >> 5] = sum;
    __syncthreads();
    float tot = 0.f;
#pragma unroll
    for (int i = 0; i < 8; i++) tot += red[i];
    const float inv = 1.f / tot;

#pragma unroll
    for (int i = 0; i < 8; i++) {
        int j = t + i * 256;
        float p = v[i] * inv;
        __nv_bfloat16 h = __float2bfloat16(p);
        __nv_bfloat16 l = __float2bfloat16(p - __bfloat162float(h));
        prow[j]            = h;   // [hi|lo|hi]
        prow[SEQ + j]      = l;
        prow[2 * SEQ + j]  = h;
    }
}

// ---------------------------------------------------------------------------
// LayerNorm over DMODEL=1024, in place.
// ---------------------------------------------------------------------------
__global__ __launch_bounds__(256)
void ln_kernel(float* __restrict__ H, const float* __restrict__ gamma,
               const float* __restrict__ beta)
{
    float* row = H + (long)blockIdx.x * DMODEL;
    const int t = threadIdx.x;
    __shared__ float redS[8];
    __shared__ float redQ[8];

    float4 v = reinterpret_cast<const float4*>(row)[t];
    float s  = v.x + v.y + v.z + v.w;
    float sq = v.x * v.x + v.y * v.y + v.z * v.z + v.w * v.w;
#pragma unroll
    for (int o = 16; o > 0; o >>= 1) {
        s  += __shfl_xor_sync(0xffffffffu, s, o);
        sq += __shfl_xor_sync(0xffffffffu, sq, o);
    }
    if ((t & 31) == 0) { redS[t >> 5] = s; redQ[t >> 5] = sq; }
    __syncthreads();
    float stot = 0.f, qtot = 0.f;
#pragma unroll
    for (int i = 0; i < 8; i++) { stot += redS[i]; qtot += redQ[i]; }

    const float mu  = stot * (1.0f / DMODEL);
    const float var = qtot * (1.0f / DMODEL) - mu * mu;
    const float inv = rsqrtf(var + 1e-5f);

    float4 gv = reinterpret_cast<const float4*>(gamma)[t];
    float4 bv = reinterpret_cast<const float4*>(beta)[t];
    float4 o;
    o.x = (v.x - mu) * inv * gv.x + bv.x;
    o.y = (v.y - mu) * inv * gv.y + bv.y;
    o.z = (v.z - mu) * inv * gv.z + bv.z;
    o.w = (v.w - mu) * inv * gv.w + bv.w;
    reinterpret_cast<float4*>(row)[t] = o;
}

// ---------------------------------------------------------------------------
// Launch
// ---------------------------------------------------------------------------
extern "C" void kernel_launch(void* const* d_in, const int* in_sizes, int n_in,
                              void* d_out, int out_size)
{
    const float* x     = (const float*)d_in[0];
    const float* Wq    = (const float*)d_in[1];
    const float* Wk    = (const float*)d_in[2];
    const float* Wv    = (const float*)d_in[3];
    const float* Wo    = (const float*)d_in[4];
    const float* gamma = (const float*)d_in[5];
    const float* beta  = (const float*)d_in[6];
    float* out = (float*)d_out;

    __nv_bfloat16 *pxs, *pWqkvt, *pWot, *pQs, *pKs, *pVts, *pPs, *pCs;
    float *pVf, *pSc;
    cudaGetSymbolAddress((void**)&pxs,    g_xs);
    cudaGetSymbolAddress((void**)&pWqkvt, g_Wqkvt);
    cudaGetSymbolAddress((void**)&pWot,   g_Wot);
    cudaGetSymbolAddress((void**)&pQs,    g_Qs);
    cudaGetSymbolAddress((void**)&pKs,    g_Ks);
    cudaGetSymbolAddress((void**)&pVf,    g_Vf);
    cudaGetSymbolAddress((void**)&pVts,   g_Vts);
    cudaGetSymbolAddress((void**)&pSc,    g_Sc);
    cudaGetSymbolAddress((void**)&pPs,    g_Ps);
    cudaGetSymbolAddress((void**)&pCs,    g_Cs);

    // --- prep operands (2 launches) ---
    split_x_kernel<<<(MTOT * DMODEL / 4) / 256, 256>>>(x, pxs);
    WPtrs wp;
    wp.in[0] = Wq;  wp.out[0] = pWqkvt;
    wp.in[1] = Wk;  wp.out[1] = pWqkvt + (size_t)DMODEL * K3;
    wp.in[2] = Wv;  wp.out[2] = pWqkvt + (size_t)2 * DMODEL * K3;
    wp.in[3] = Wo;  wp.out[3] = pWot;
    dim3 tb(32, 8);
    transpose_split4_kernel<<<dim3(32, 32, 4), tb>>>(wp);

    // --- fused QKV projection: N=3072 over concat weights (K'=3072) ---
    dim3 gqkv(3 * DMODEL / 128, MTOT / 128, 1);   // (24, 64, 1) = 1536 CTAs
    mma_gemm<2><<<gqkv, 128>>>(pxs, pWqkvt, nullptr, MTOT, 3 * DMODEL, K3,
                               0, 0, 0, 1.f, 0, 0);

    // V^T split per batch
    transpose_split_kernel<<<dim3(DMODEL / 32, SEQ / 32, BATCH), tb>>>(
        pVf, pVts, SEQ, DMODEL, (long)SEQ * DMODEL, (long)DMODEL * K3S);

    // --- scores = (Q K^T)/sqrt(dk), per batch ---
    dim3 g2(SEQ / 128, SEQ / 128, BATCH);     // (16, 16, 4)
    mma_gemm<0><<<g2, 128>>>(pQs, pKs, pSc, SEQ, SEQ, K3,
                             (long)SEQ * K3, (long)SEQ * K3,
                             (long)SEQ * SEQ, 0.03125f, 0, 0);

    // --- softmax -> split probs ---
    softmax_split_kernel<<<MTOT, 256>>>(pSc, pPs);

    // --- ctx = P V, per batch (K'=6144) ---
    dim3 g3(DMODEL / 128, SEQ / 128, BATCH);  // (8, 16, 4)
    mma_gemm<1><<<g3, 128>>>(pPs, pVts, pCs, SEQ, DMODEL, K3S,
                             (long)SEQ * K3S, (long)DMODEL * K3S,
                             (long)SEQ * K3, 1.f, DMODEL, /*patB=*/0);

    // --- out proj -> d_out, then LN ---
    dim3 g1(DMODEL / 128, MTOT / 128, 1);     // (8, 64, 1)
    mma_gemm<0><<<g1, 128>>>(pCs, pWot, out, MTOT, DMODEL, K3,
                             0, 0, 0, 1.f, 0, 0);
    ln_kernel<<<MTOT, 256>>>(out, gamma, beta);
}